// round 2
// baseline (speedup 1.0000x reference)
#include <cuda_runtime.h>
#include <math.h>

// Problem constants
#define TT 8
#define HS 48
#define FN 2304          // 48*48
#define FL 1024          // C*S*S
#define CC 64
#define HH 192
#define WW 192
#define NB 32            // n*t*G

// ---------------- scratch (device globals; no runtime allocation) ----------------
__device__ float g_iT [(size_t)TT*FN*FL];   // idx1 transposed: [t][srcpix][c]
__device__ float g_s1T[(size_t)TT*FN*FL];
__device__ float g_s2T[(size_t)TT*FN*FL];
__device__ float g_s3T[(size_t)TT*FN*FL];
__device__ float g_CN [(size_t)FN*FL];      // l2-normalized unfold(curr): [f][c]
__device__ float g_conv[(size_t)NB*256*FN]; // grouped-conv output
__device__ float g_gp [(size_t)NB*FN*2];    // bilinear sample coords (x,y) in pixel units
__device__ float g_csoft[FN];
__device__ int   g_cidx [FN];
__device__ int   g_gidx [TT*FN];            // nearest grid: src pixel index or -1
__device__ float g_inorm[TT*FN];            // 1/max(||idx1[t,:,src]||,1e-12)
__device__ float g_fused[(size_t)192*HH*WW];// fusion-conv input (3*64 ch)

// ---------------- K0: nearest grid indices + validity ----------------
__global__ void k_grid(const float* __restrict__ loc){
    int i = blockIdx.x*blockDim.x + threadIdx.x;
    if (i >= TT*FN) return;
    int t = i / FN, f = i - t*FN;
    float lx = loc[(t*2+0)*FN + f];   // x coordinate
    float ly = loc[(t*2+1)*FN + f];   // y coordinate
    int ix = __float2int_rn(lx);      // round-half-even == jnp.round
    int iy = __float2int_rn(ly);
    bool valid = (ix>=0 && ix<HS && iy>=0 && iy<HS);
    g_gidx[i] = valid ? (iy*HS + ix) : -1;
}

// ---------------- K1: tiled transpose of the 4 big tensors to pixel-major ----------------
__global__ void k_transpose(const float* __restrict__ a0, const float* __restrict__ a1,
                            const float* __restrict__ a2, const float* __restrict__ a3){
    __shared__ float tile[32][33];
    int z = blockIdx.z;
    int which = z >> 3, t = z & 7;
    const float* src; float* dst;
    switch (which){
        case 0: src = a0; dst = g_iT;  break;
        case 1: src = a1; dst = g_s1T; break;
        case 2: src = a2; dst = g_s2T; break;
        default:src = a3; dst = g_s3T; break;
    }
    src += (size_t)t*FL*FN;
    dst += (size_t)t*FN*FL;
    int f0 = blockIdx.x*32, c0 = blockIdx.y*32;
    int tx = threadIdx.x, ty = threadIdx.y;
    #pragma unroll
    for (int r = 0; r < 32; r += 8)
        tile[ty+r][tx] = src[(size_t)(c0+ty+r)*FN + (f0+tx)];
    __syncthreads();
    #pragma unroll
    for (int r = 0; r < 32; r += 8)
        dst[(size_t)(f0+ty+r)*FL + (c0+tx)] = tile[tx][ty+r];
}

// ---------------- K2: per-source-pixel inverse norm of idx1 ----------------
__global__ void k_inorm(){
    int i = blockIdx.x;                 // t*FN + srcpix
    int tid = threadIdx.x;
    const float* base = g_iT + (size_t)i*FL;
    float ss = 0.f;
    #pragma unroll
    for (int k = 0; k < 4; k++){ float x = base[k*256 + tid]; ss += x*x; }
    for (int o = 16; o > 0; o >>= 1) ss += __shfl_xor_sync(~0u, ss, o);
    __shared__ float ws[8];
    if ((tid & 31) == 0) ws[tid>>5] = ss;
    __syncthreads();
    if (tid == 0){
        float s = 0.f;
        #pragma unroll
        for (int k = 0; k < 8; k++) s += ws[k];
        g_inorm[i] = 1.0f / fmaxf(sqrtf(s), 1e-12f);
    }
}

// ---------------- K3: build normalized unfold(curr) in pixel-major ----------------
__global__ void k_cn(const float* __restrict__ curr){
    int f = blockIdx.x, tid = threadIdx.x;
    int fy = f / HS, fx = f - fy*HS;
    float v[4]; float ss = 0.f;
    #pragma unroll
    for (int k = 0; k < 4; k++){
        int cf = k*256 + tid;
        int c = cf >> 4, rem = cf & 15, sy = rem >> 2, sx = rem & 3;
        float x = curr[((size_t)c*HH + (fy*4+sy))*WW + (fx*4+sx)];
        v[k] = x; ss += x*x;
    }
    for (int o = 16; o > 0; o >>= 1) ss += __shfl_xor_sync(~0u, ss, o);
    __shared__ float ws[8]; __shared__ float invs;
    if ((tid & 31) == 0) ws[tid>>5] = ss;
    __syncthreads();
    if (tid == 0){
        float s = 0.f;
        #pragma unroll
        for (int k = 0; k < 8; k++) s += ws[k];
        invs = 1.0f / fmaxf(sqrtf(s), 1e-12f);
    }
    __syncthreads();
    float iv = invs;
    #pragma unroll
    for (int k = 0; k < 4; k++) g_CN[(size_t)f*FL + k*256 + tid] = v[k]*iv;
}

// ---------------- K4: grouped 5x5 conv (groups=256, 2 in-ch per group) ----------------
__global__ void k_conv(const float* __restrict__ wtdw, const float* __restrict__ btdw){
    int o = blockIdx.x;                 // 0..255 output channel (= group)
    int b = blockIdx.y;                 // 0..31, b = t*4+g
    int t = b >> 2, g = b & 3;
    __shared__ float p0[52*52], p1[52*52], w[50];
    int tid = threadIdx.x;
    if (tid < 50) w[tid] = wtdw[o*50 + tid];
    bool isQ = (o < 128);
    int ch0 = isQ ? (g*256 + 2*o) : (g*256 + 2*o - 256);
    for (int i = tid; i < 52*52; i += 256){
        int yy = i/52 - 2, xx = i%52 - 2;
        float v0 = 0.f, v1 = 0.f;
        if (yy >= 0 && yy < HS && xx >= 0 && xx < HS){
            int f = yy*HS + xx;
            if (isQ){
                const float* cp = g_CN + (size_t)f*FL + ch0;
                v0 = cp[0]; v1 = cp[1];
            } else {
                int idx = g_gidx[t*FN + f];
                if (idx >= 0){
                    float inr = g_inorm[t*FN + idx];
                    const float* ip = g_iT + ((size_t)t*FN + idx)*FL + ch0;
                    v0 = ip[0]*inr; v1 = ip[1]*inr;
                }
            }
        }
        p0[i] = v0; p1[i] = v1;
    }
    __syncthreads();
    float bias = btdw[o];
    for (int f = tid; f < FN; f += 256){
        int y = f / HS, x = f - y*HS;
        float acc = bias;
        #pragma unroll
        for (int ky = 0; ky < 5; ky++){
            #pragma unroll
            for (int kx = 0; kx < 5; kx++){
                acc += w[ky*5+kx]      * p0[(y+ky)*52 + x+kx];
                acc += w[25 + ky*5+kx] * p1[(y+ky)*52 + x+kx];
            }
        }
        g_conv[((size_t)b*256 + o)*FN + f] = acc;
    }
}

// ---------------- K5: LayerNorm + exact GELU + 1x1 conv + tanh -> sample coords ----------------
__global__ void k_ln(const float* __restrict__ lng, const float* __restrict__ lnb,
                     const float* __restrict__ wtpw){
    __shared__ float tile[256*33];
    __shared__ float sgam[256], sbet[256], w0[256], w1[256];
    int b = blockIdx.y;
    int pixbase = blockIdx.x * 32;
    int tid = threadIdx.x;
    sgam[tid] = lng[tid]; sbet[tid] = lnb[tid];
    w0[tid] = wtpw[tid];  w1[tid]  = wtpw[256 + tid];
    for (int i = tid; i < 256*32; i += 256){
        int ch = i >> 5, p = i & 31;
        tile[ch*33 + p] = g_conv[((size_t)b*256 + ch)*FN + pixbase + p];
    }
    __syncthreads();
    int lane = tid & 31, wid = tid >> 5;
    for (int q = 0; q < 4; q++){
        int p = wid*4 + q;
        float xv[8]; float s = 0.f, ss = 0.f;
        #pragma unroll
        for (int k = 0; k < 8; k++){
            float x = tile[(lane + 32*k)*33 + p];
            xv[k] = x; s += x; ss += x*x;
        }
        for (int o = 16; o > 0; o >>= 1){
            s  += __shfl_xor_sync(~0u, s,  o);
            ss += __shfl_xor_sync(~0u, ss, o);
        }
        float mean = s * (1.0f/256.0f);
        float var  = ss * (1.0f/256.0f) - mean*mean;
        float rstd = rsqrtf(var + 1e-5f);
        float a0 = 0.f, a1 = 0.f;
        #pragma unroll
        for (int k = 0; k < 8; k++){
            int ch = lane + 32*k;
            float y = (xv[k] - mean)*rstd*sgam[ch] + sbet[ch];
            float gl = 0.5f*y*(1.0f + erff(y*0.70710678118654752f));
            a0 += gl*w0[ch]; a1 += gl*w1[ch];
        }
        for (int o = 16; o > 0; o >>= 1){
            a0 += __shfl_xor_sync(~0u, a0, o);
            a1 += __shfl_xor_sync(~0u, a1, o);
        }
        if (lane == 0){
            int pix = pixbase + p;
            int py = pix / HS, px = pix - py*HS;
            float o0 = tanhf(a0) * (2.0f/48.0f);   // y-offset channel * ORF/Hk
            float o1 = tanhf(a1) * (2.0f/48.0f);   // x-offset channel * ORF/Wk
            float ry = (0.5f + py)*(2.0f/48.0f) - 1.0f;
            float rx = (0.5f + px)*(2.0f/48.0f) - 1.0f;
            g_gp[((size_t)b*FN + pix)*2 + 0] = (o1 + rx + 1.0f)*0.5f*47.0f; // x
            g_gp[((size_t)b*FN + pix)*2 + 1] = (o0 + ry + 1.0f)*0.5f*47.0f; // y
        }
    }
}

// ---------------- K6: mat = <bilinear(tk), cn>, max/argmax over t ----------------
__global__ void k_mat(){
    int f = blockIdx.x, tid = threadIdx.x;
    float cn4[4];
    #pragma unroll
    for (int g = 0; g < 4; g++) cn4[g] = g_CN[(size_t)f*FL + g*256 + tid];
    __shared__ float ws[8];
    float best = -1e30f; int besti = 0;
    for (int t = 0; t < TT; t++){
        float acc = 0.f;
        #pragma unroll
        for (int g = 0; g < 4; g++){
            int b = t*4 + g;
            float sx = g_gp[((size_t)b*FN + f)*2 + 0];
            float sy = g_gp[((size_t)b*FN + f)*2 + 1];
            float x0f = floorf(sx), y0f = floorf(sy);
            float wx = sx - x0f, wy = sy - y0f;
            int x0 = (int)x0f, y0 = (int)y0f;
            float v = 0.f;
            #pragma unroll
            for (int dy = 0; dy < 2; dy++){
                #pragma unroll
                for (int dx = 0; dx < 2; dx++){
                    int cy = y0 + dy, cx = x0 + dx;
                    if (cy >= 0 && cy < HS && cx >= 0 && cx < HS){
                        int idx = g_gidx[t*FN + cy*HS + cx];
                        if (idx >= 0){
                            float wgt = (dy ? wy : 1.0f-wy) * (dx ? wx : 1.0f-wx);
                            v += wgt * g_iT[((size_t)t*FN + idx)*FL + g*256 + tid]
                                     * g_inorm[t*FN + idx];
                        }
                    }
                }
            }
            acc += v * cn4[g];
        }
        for (int o = 16; o > 0; o >>= 1) acc += __shfl_xor_sync(~0u, acc, o);
        if ((tid & 31) == 0) ws[tid>>5] = acc;
        __syncthreads();
        if (tid == 0){
            float s = 0.f;
            #pragma unroll
            for (int k = 0; k < 8; k++) s += ws[k];
            if (s > best){ best = s; besti = t; }  // first-max wins (strict >)
        }
        __syncthreads();
    }
    if (tid == 0){ g_csoft[f] = best; g_cidx[f] = besti; }
}

// ---------------- K7: gather s1/s2/s3 at argmax time, bilinear, fold ----------------
__global__ void k_sg(){
    int f = blockIdx.x, tid = threadIdx.x;
    int t = g_cidx[f];
    int fy = f / HS, fx = f - fy*HS;
    for (int g = 0; g < 4; g++){
        int b = t*4 + g;
        float sx = g_gp[((size_t)b*FN + f)*2 + 0];
        float sy = g_gp[((size_t)b*FN + f)*2 + 1];
        float x0f = floorf(sx), y0f = floorf(sy);
        float wx = sx - x0f, wy = sy - y0f;
        int x0 = (int)x0f, y0 = (int)y0f;
        float v0 = 0.f, v1 = 0.f, v2 = 0.f;
        #pragma unroll
        for (int dy = 0; dy < 2; dy++){
            #pragma unroll
            for (int dx = 0; dx < 2; dx++){
                int cy = y0 + dy, cx = x0 + dx;
                if (cy >= 0 && cy < HS && cx >= 0 && cx < HS){
                    int idx = g_gidx[t*FN + cy*HS + cx];
                    if (idx >= 0){
                        float wgt = (dy ? wy : 1.0f-wy) * (dx ? wx : 1.0f-wx);
                        size_t off = ((size_t)t*FN + idx)*FL + g*256 + tid;
                        v0 += wgt * g_s1T[off];
                        v1 += wgt * g_s2T[off];
                        v2 += wgt * g_s3T[off];
                    }
                }
            }
        }
        int cf = g*256 + tid;
        int c = cf >> 4, rem = cf & 15, syy = rem >> 2, sxx = rem & 3;
        size_t base = (size_t)(fy*4 + syy)*WW + (fx*4 + sxx);
        g_fused[(size_t)(c      )*HH*WW + base] = v0;
        g_fused[(size_t)(64  + c)*HH*WW + base] = v1;
        g_fused[(size_t)(128 + c)*HH*WW + base] = v2;
    }
}

// ---------------- K8: 3x3 fusion conv (192->64) + bias, * csoft_fold + anchor ----------------
__global__ void k_fus(const float* __restrict__ wfus, const float* __restrict__ bfus,
                      const float* __restrict__ anchor, float* __restrict__ out){
    int tid = threadIdx.x;
    int tx = tid & 15, ty = tid >> 4;
    int X0 = blockIdx.x*16, Y0 = blockIdx.y*16, oc0 = blockIdx.z*16;
    __shared__ float tile[18*18];
    __shared__ float wsm[16*9];
    float acc[16];
    #pragma unroll
    for (int i = 0; i < 16; i++) acc[i] = 0.f;
    for (int ic = 0; ic < 192; ic++){
        __syncthreads();
        for (int i = tid; i < 18*18; i += 256){
            int yy = Y0 + i/18 - 1, xx = X0 + i%18 - 1;
            tile[i] = (yy >= 0 && yy < HH && xx >= 0 && xx < WW)
                      ? g_fused[(size_t)ic*HH*WW + (size_t)yy*WW + xx] : 0.f;
        }
        if (tid < 144) wsm[tid] = wfus[((size_t)(oc0 + tid/9)*192 + ic)*9 + (tid % 9)];
        __syncthreads();
        float in9[9];
        #pragma unroll
        for (int ky = 0; ky < 3; ky++)
            #pragma unroll
            for (int kx = 0; kx < 3; kx++)
                in9[ky*3+kx] = tile[(ty+ky)*18 + tx+kx];
        #pragma unroll
        for (int oc = 0; oc < 16; oc++){
            float a = acc[oc];
            #pragma unroll
            for (int k = 0; k < 9; k++) a += wsm[oc*9+k]*in9[k];
            acc[oc] = a;
        }
    }
    int Y = Y0 + ty, X = X0 + tx;
    float cs = g_csoft[(Y>>2)*HS + (X>>2)];
    #pragma unroll
    for (int oc = 0; oc < 16; oc++){
        int c = oc0 + oc;
        size_t p = (size_t)c*HH*WW + (size_t)Y*WW + X;
        out[p] = (acc[oc] + bfus[c])*cs + anchor[p];
    }
}

// ---------------- launch ----------------
extern "C" void kernel_launch(void* const* d_in, const int* in_sizes, int n_in,
                              void* d_out, int out_size){
    (void)in_sizes; (void)n_in; (void)out_size;
    const float* curr   = (const float*)d_in[0];
    const float* idx1   = (const float*)d_in[1];
    const float* anchor = (const float*)d_in[2];
    const float* s1     = (const float*)d_in[3];
    const float* s2     = (const float*)d_in[4];
    const float* s3     = (const float*)d_in[5];
    const float* loc    = (const float*)d_in[6];
    const float* wtdw   = (const float*)d_in[7];
    const float* btdw   = (const float*)d_in[8];
    const float* lng    = (const float*)d_in[9];
    const float* lnb    = (const float*)d_in[10];
    const float* wtpw   = (const float*)d_in[11];
    const float* wfus   = (const float*)d_in[12];
    const float* bfus   = (const float*)d_in[13];
    float* out = (float*)d_out;

    k_grid<<<(TT*FN + 255)/256, 256>>>(loc);

    dim3 tb(32, 8);
    dim3 tg(FN/32, FL/32, 32);   // 4 tensors * 8 time steps
    k_transpose<<<tg, tb>>>(idx1, s1, s2, s3);

    k_inorm<<<TT*FN, 256>>>();
    k_cn   <<<FN, 256>>>(curr);
    k_conv <<<dim3(256, NB), 256>>>(wtdw, btdw);
    k_ln   <<<dim3(FN/32, NB), 256>>>(lng, lnb, wtpw);
    k_mat  <<<FN, 256>>>();
    k_sg   <<<FN, 256>>>();
    k_fus  <<<dim3(WW/16, HH/16, 4), 256>>>(wfus, bfus, anchor, out);
}

// round 3
// speedup vs baseline: 1.3254x; 1.3254x over previous
#include <cuda_runtime.h>
#include <math.h>

#define TT 8
#define HS 48
#define FN 2304          // 48*48
#define FL 1024          // C*S*S
#define HH 192
#define WW 192
#define NB 32            // n*t*G

typedef unsigned long long ull;

__device__ __forceinline__ ull pk2(float lo, float hi){
    ull r; asm("mov.b64 %0,{%1,%2};" : "=l"(r) : "f"(lo), "f"(hi)); return r;
}
__device__ __forceinline__ ull fma2(ull a, ull b, ull c){
    ull d; asm("fma.rn.f32x2 %0,%1,%2,%3;" : "=l"(d) : "l"(a), "l"(b), "l"(c)); return d;
}
__device__ __forceinline__ float2 upk(ull a){
    float2 f; asm("mov.b64 {%0,%1},%2;" : "=f"(f.x), "=f"(f.y) : "l"(a)); return f;
}

// ---------------- scratch ----------------
__device__ float g_iT [(size_t)TT*FN*FL];
__device__ float g_s1T[(size_t)TT*FN*FL];
__device__ float g_s2T[(size_t)TT*FN*FL];
__device__ float g_s3T[(size_t)TT*FN*FL];
__device__ float g_CN [(size_t)FN*FL];
__device__ float g_conv[(size_t)NB*256*FN];
__device__ float g_gp [(size_t)NB*FN*2];
__device__ float g_csoft[FN];
__device__ int   g_cidx [FN];
__device__ int   g_gidx [TT*FN];
__device__ float g_inorm[TT*FN];
__device__ float g_sspart[(size_t)32*TT*FN];   // per-c-chunk partial sums of squares
__device__ float g_fused[(size_t)192*HH*WW];

// ---------------- K0: nearest grid indices ----------------
__global__ void k_grid(const float* __restrict__ loc){
    int i = blockIdx.x*blockDim.x + threadIdx.x;
    if (i >= TT*FN) return;
    int t = i / FN, f = i - t*FN;
    float lx = loc[(t*2+0)*FN + f];
    float ly = loc[(t*2+1)*FN + f];
    int ix = __float2int_rn(lx);
    int iy = __float2int_rn(ly);
    bool valid = (ix>=0 && ix<HS && iy>=0 && iy<HS);
    g_gidx[i] = valid ? (iy*HS + ix) : -1;
}

// ---------------- K1: tiled transpose + fused ||idx1||^2 partials ----------------
__global__ void k_transpose(const float* __restrict__ a0, const float* __restrict__ a1,
                            const float* __restrict__ a2, const float* __restrict__ a3){
    __shared__ float tile[32][33];
    int z = blockIdx.z;
    int which = z >> 3, t = z & 7;
    const float* src; float* dst;
    switch (which){
        case 0: src = a0; dst = g_iT;  break;
        case 1: src = a1; dst = g_s1T; break;
        case 2: src = a2; dst = g_s2T; break;
        default:src = a3; dst = g_s3T; break;
    }
    src += (size_t)t*FL*FN;
    dst += (size_t)t*FN*FL;
    int f0 = blockIdx.x*32, c0 = blockIdx.y*32;
    int tx = threadIdx.x, ty = threadIdx.y;
    #pragma unroll
    for (int r = 0; r < 32; r += 8)
        tile[ty+r][tx] = src[(size_t)(c0+ty+r)*FN + (f0+tx)];
    __syncthreads();
    #pragma unroll
    for (int r = 0; r < 32; r += 8)
        dst[(size_t)(f0+ty+r)*FL + (c0+tx)] = tile[tx][ty+r];
    if (which == 0){
        #pragma unroll
        for (int r = 0; r < 32; r += 8){
            float x = tile[tx][ty+r];
            float s = x*x;
            #pragma unroll
            for (int o = 16; o > 0; o >>= 1) s += __shfl_xor_sync(~0u, s, o);
            if (tx == 0)
                g_sspart[(size_t)blockIdx.y*(TT*FN) + t*FN + (f0+ty+r)] = s;
        }
    }
}

// ---------------- K2: finalize inverse norms ----------------
__global__ void k_normfin(){
    int i = blockIdx.x*blockDim.x + threadIdx.x;
    if (i >= TT*FN) return;
    float s = 0.f;
    #pragma unroll
    for (int k = 0; k < 32; k++) s += g_sspart[(size_t)k*(TT*FN) + i];
    g_inorm[i] = 1.0f / fmaxf(sqrtf(s), 1e-12f);
}

// ---------------- K3: normalized unfold(curr), pixel-major ----------------
__global__ void k_cn(const float* __restrict__ curr){
    int f = blockIdx.x, tid = threadIdx.x;
    int fy = f / HS, fx = f - fy*HS;
    float v[4]; float ss = 0.f;
    #pragma unroll
    for (int k = 0; k < 4; k++){
        int cf = k*256 + tid;
        int c = cf >> 4, rem = cf & 15, sy = rem >> 2, sx = rem & 3;
        float x = curr[((size_t)c*HH + (fy*4+sy))*WW + (fx*4+sx)];
        v[k] = x; ss += x*x;
    }
    for (int o = 16; o > 0; o >>= 1) ss += __shfl_xor_sync(~0u, ss, o);
    __shared__ float ws[8]; __shared__ float invs;
    if ((tid & 31) == 0) ws[tid>>5] = ss;
    __syncthreads();
    if (tid == 0){
        float s = 0.f;
        #pragma unroll
        for (int k = 0; k < 8; k++) s += ws[k];
        invs = 1.0f / fmaxf(sqrtf(s), 1e-12f);
    }
    __syncthreads();
    float iv = invs;
    #pragma unroll
    for (int k = 0; k < 4; k++) g_CN[(size_t)f*FL + k*256 + tid] = v[k]*iv;
}

// ---------------- K4: grouped 5x5 conv, 4 o per block, register sliding window ----------------
__global__ void __launch_bounds__(192) k_conv(const float* __restrict__ wtdw,
                                              const float* __restrict__ btdw){
    extern __shared__ float p[];              // 8 planes x 52*52
    __shared__ float w[200];                  // 4 o x 50 taps
    __shared__ float bsm[4];
    int oq = blockIdx.x;                      // o quartet 0..63
    int b  = blockIdx.y;                      // 0..31
    int t = b >> 2, g = b & 3;
    int tid = threadIdx.x;
    int o0 = oq*4;
    bool isQ = (o0 < 128);
    int ch0 = g*256 + 2*o0 - (isQ ? 0 : 256);
    for (int i = tid; i < 200; i += 192) w[i] = wtdw[(size_t)o0*50 + i];
    if (tid < 4) bsm[tid] = btdw[o0 + tid];
    // fill: 2704 pixels * 8 channels via 2 float4 per pixel
    for (int i = tid; i < 2704*2; i += 192){
        int pix = i >> 1, half = i & 1;
        int yy = pix/52 - 2, xx = pix%52 - 2;
        float4 v = make_float4(0.f,0.f,0.f,0.f);
        if (yy >= 0 && yy < HS && xx >= 0 && xx < HS){
            int f = yy*HS + xx;
            if (isQ){
                v = *(const float4*)(g_CN + (size_t)f*FL + ch0 + half*4);
            } else {
                int idx = g_gidx[t*FN + f];
                if (idx >= 0){
                    float inr = g_inorm[t*FN + idx];
                    v = *(const float4*)(g_iT + ((size_t)t*FN + idx)*FL + ch0 + half*4);
                    v.x *= inr; v.y *= inr; v.z *= inr; v.w *= inr;
                }
            }
        }
        int cb = half*4;
        p[(cb+0)*2704 + pix] = v.x;
        p[(cb+1)*2704 + pix] = v.y;
        p[(cb+2)*2704 + pix] = v.z;
        p[(cb+3)*2704 + pix] = v.w;
    }
    __syncthreads();
    int x  = tid % 48;
    int ys = tid / 48;                        // 0..3 row strip
    float acc[4][12];
    #pragma unroll
    for (int o = 0; o < 4; o++)
        #pragma unroll
        for (int j = 0; j < 12; j++) acc[o][j] = 0.f;
    #pragma unroll
    for (int c = 0; c < 8; c++){
        const float* wb = w + (c>>1)*50 + (c&1)*25;
        const float* pc = p + c*2704;
        #pragma unroll
        for (int kx = 0; kx < 5; kx++){
            float v[16];
            #pragma unroll
            for (int r = 0; r < 16; r++) v[r] = pc[(ys*12 + r)*52 + x + kx];
            #pragma unroll
            for (int ky = 0; ky < 5; ky++){
                float wv = wb[ky*5 + kx];
                #pragma unroll
                for (int j = 0; j < 12; j++) acc[c>>1][j] += wv * v[j+ky];
            }
        }
    }
    #pragma unroll
    for (int o = 0; o < 4; o++){
        float bias = bsm[o];
        #pragma unroll
        for (int j = 0; j < 12; j++)
            g_conv[((size_t)b*256 + o0 + o)*FN + (ys*12 + j)*48 + x] = acc[o][j] + bias;
    }
}

// ---------------- K5: LayerNorm + GELU + 1x1 conv + tanh -> coords ----------------
__global__ void k_ln(const float* __restrict__ lng, const float* __restrict__ lnb,
                     const float* __restrict__ wtpw){
    __shared__ float tile[256*33];
    __shared__ float sgam[256], sbet[256], w0[256], w1[256];
    int b = blockIdx.y;
    int pixbase = blockIdx.x * 32;
    int tid = threadIdx.x;
    sgam[tid] = lng[tid]; sbet[tid] = lnb[tid];
    w0[tid] = wtpw[tid];  w1[tid]  = wtpw[256 + tid];
    for (int i = tid; i < 256*32; i += 256){
        int ch = i >> 5, pp = i & 31;
        tile[ch*33 + pp] = g_conv[((size_t)b*256 + ch)*FN + pixbase + pp];
    }
    __syncthreads();
    int lane = tid & 31, wid = tid >> 5;
    for (int q = 0; q < 4; q++){
        int pp = wid*4 + q;
        float xv[8]; float s = 0.f, ss = 0.f;
        #pragma unroll
        for (int k = 0; k < 8; k++){
            float x = tile[(lane + 32*k)*33 + pp];
            xv[k] = x; s += x; ss += x*x;
        }
        for (int o = 16; o > 0; o >>= 1){
            s  += __shfl_xor_sync(~0u, s,  o);
            ss += __shfl_xor_sync(~0u, ss, o);
        }
        float mean = s * (1.0f/256.0f);
        float var  = ss * (1.0f/256.0f) - mean*mean;
        float rstd = rsqrtf(var + 1e-5f);
        float a0 = 0.f, a1 = 0.f;
        #pragma unroll
        for (int k = 0; k < 8; k++){
            int ch = lane + 32*k;
            float y = (xv[k] - mean)*rstd*sgam[ch] + sbet[ch];
            float gl = 0.5f*y*(1.0f + erff(y*0.70710678118654752f));
            a0 += gl*w0[ch]; a1 += gl*w1[ch];
        }
        for (int o = 16; o > 0; o >>= 1){
            a0 += __shfl_xor_sync(~0u, a0, o);
            a1 += __shfl_xor_sync(~0u, a1, o);
        }
        if (lane == 0){
            int pix = pixbase + pp;
            int py = pix / HS, px = pix - py*HS;
            float o0 = tanhf(a0) * (2.0f/48.0f);
            float o1 = tanhf(a1) * (2.0f/48.0f);
            float ry = (0.5f + py)*(2.0f/48.0f) - 1.0f;
            float rx = (0.5f + px)*(2.0f/48.0f) - 1.0f;
            g_gp[((size_t)b*FN + pix)*2 + 0] = (o1 + rx + 1.0f)*0.5f*47.0f;
            g_gp[((size_t)b*FN + pix)*2 + 1] = (o0 + ry + 1.0f)*0.5f*47.0f;
        }
    }
}

// ---------------- K6: mat + max/argmax, warp-per-t ----------------
__global__ void k_mat(){
    int f = blockIdx.x, tid = threadIdx.x;
    __shared__ float cns[1024];
    __shared__ float part[8];
    #pragma unroll
    for (int k = 0; k < 4; k++) cns[k*256 + tid] = g_CN[(size_t)f*FL + k*256 + tid];
    __syncthreads();
    int w = tid >> 5, lane = tid & 31;   // w = t
    float acc = 0.f;
    #pragma unroll
    for (int g = 0; g < 4; g++){
        int b = w*4 + g;
        float sx = g_gp[((size_t)b*FN + f)*2 + 0];
        float sy = g_gp[((size_t)b*FN + f)*2 + 1];
        float x0f = floorf(sx), y0f = floorf(sy);
        float wx = sx - x0f, wy = sy - y0f;
        int x0 = (int)x0f, y0 = (int)y0f;
        float vs[8];
        #pragma unroll
        for (int k = 0; k < 8; k++) vs[k] = 0.f;
        #pragma unroll
        for (int dy = 0; dy < 2; dy++){
            #pragma unroll
            for (int dx = 0; dx < 2; dx++){
                int cy = y0 + dy, cx = x0 + dx;
                if (cy >= 0 && cy < HS && cx >= 0 && cx < HS){
                    int idx = g_gidx[w*FN + cy*HS + cx];
                    if (idx >= 0){
                        float sc = ((dy ? wy : 1.0f-wy) * (dx ? wx : 1.0f-wx))
                                   * g_inorm[w*FN + idx];
                        const float* ip = g_iT + ((size_t)w*FN + idx)*FL + g*256;
                        #pragma unroll
                        for (int k = 0; k < 8; k++) vs[k] += sc * ip[k*32 + lane];
                    }
                }
            }
        }
        #pragma unroll
        for (int k = 0; k < 8; k++) acc += vs[k] * cns[g*256 + k*32 + lane];
    }
    for (int o = 16; o > 0; o >>= 1) acc += __shfl_xor_sync(~0u, acc, o);
    if (lane == 0) part[w] = acc;
    __syncthreads();
    if (tid == 0){
        float best = part[0]; int besti = 0;
        #pragma unroll
        for (int t = 1; t < 8; t++){
            if (part[t] > best){ best = part[t]; besti = t; }
        }
        g_csoft[f] = best; g_cidx[f] = besti;
    }
}

// ---------------- K7: argmax-time bilinear gather, fold, coalesced writes ----------------
__global__ void k_sg(){
    int tid = threadIdx.x;
    int fy = blockIdx.x / 24, fxh = blockIdx.x % 24;
    __shared__ float sv[3*1024*2];
    for (int half = 0; half < 2; half++){
        int f = fy*HS + fxh*2 + half;
        int t = g_cidx[f];
        #pragma unroll
        for (int g = 0; g < 4; g++){
            int b = t*4 + g;
            float sx = g_gp[((size_t)b*FN + f)*2 + 0];
            float sy = g_gp[((size_t)b*FN + f)*2 + 1];
            float x0f = floorf(sx), y0f = floorf(sy);
            float wx = sx - x0f, wy = sy - y0f;
            int x0 = (int)x0f, y0 = (int)y0f;
            float v0 = 0.f, v1 = 0.f, v2 = 0.f;
            #pragma unroll
            for (int dy = 0; dy < 2; dy++){
                #pragma unroll
                for (int dx = 0; dx < 2; dx++){
                    int cy = y0 + dy, cx = x0 + dx;
                    if (cy >= 0 && cy < HS && cx >= 0 && cx < HS){
                        int idx = g_gidx[t*FN + cy*HS + cx];
                        if (idx >= 0){
                            float wgt = (dy ? wy : 1.0f-wy) * (dx ? wx : 1.0f-wx);
                            size_t off = ((size_t)t*FN + idx)*FL + g*256 + tid;
                            v0 += wgt * g_s1T[off];
                            v1 += wgt * g_s2T[off];
                            v2 += wgt * g_s3T[off];
                        }
                    }
                }
            }
            int cf = g*256 + tid;
            sv[(0*1024 + cf)*2 + half] = v0;
            sv[(1*1024 + cf)*2 + half] = v1;
            sv[(2*1024 + cf)*2 + half] = v2;
        }
    }
    __syncthreads();
    int X0 = fxh*8;
    for (int i = tid; i < 768; i += 256){
        int tn = i >> 8, rem = i & 255, c_out = rem >> 2, sy2 = rem & 3;
        int base = (tn*1024 + c_out*16 + sy2*4)*2;
        float4 a = make_float4(sv[base+0], sv[base+2], sv[base+4], sv[base+6]);
        float4 bb = make_float4(sv[base+1], sv[base+3], sv[base+5], sv[base+7]);
        int ch = tn*64 + c_out;
        size_t p0 = (size_t)ch*HH*WW + (size_t)(fy*4 + sy2)*WW + X0;
        *(float4*)(g_fused + p0)     = a;
        *(float4*)(g_fused + p0 + 4) = bb;
    }
}

// ---------------- K8: 3x3 fusion conv with packed f32x2 FMA ----------------
__global__ void __launch_bounds__(256, 2) k_fus(const float* __restrict__ wfus,
                                                const float* __restrict__ bfus,
                                                const float* __restrict__ anchor,
                                                float* __restrict__ out){
    __shared__ float tile[2][18*66];
    __shared__ float wsm[2][72];
    int tid = threadIdx.x;
    int X0 = blockIdx.x*64, Y0 = blockIdx.y*16, oc0 = blockIdx.z*8;
    int w_ = tid >> 5, lane = tid & 31;
    int ocg = w_ & 1, yg = w_ >> 1;
    int oct = lane & 7, yl = lane >> 3;
    int ylocal = yg*4 + yl;
    int y = Y0 + ylocal;
    int xb = X0 + oct*8;
    ull acc[16];
    #pragma unroll
    for (int i = 0; i < 16; i++) acc[i] = 0ull;

    for (int ic0 = 0; ic0 < 192; ic0 += 2){
        __syncthreads();
        #pragma unroll
        for (int s = 0; s < 2; s++){
            int ic = ic0 + s;
            for (int i = tid; i < 18*66; i += 256){
                int r = i/66, cc = i%66;
                int yy = Y0 + r - 1, xx = X0 + cc - 1;
                tile[s][i] = (yy >= 0 && yy < HH && xx >= 0 && xx < WW)
                             ? g_fused[(size_t)ic*HH*WW + (size_t)yy*WW + xx] : 0.f;
            }
            if (tid < 72)
                wsm[s][tid] = wfus[((size_t)(oc0 + tid/9)*192 + ic)*9 + (tid % 9)];
        }
        __syncthreads();
        #pragma unroll
        for (int s = 0; s < 2; s++){
            #pragma unroll
            for (int r = 0; r < 3; r++){
                const float* rowp = &tile[s][(ylocal + r)*66 + oct*8];
                float v[10];
                #pragma unroll
                for (int q = 0; q < 5; q++){
                    float2 a2 = *(const float2*)(rowp + 2*q);
                    v[2*q] = a2.x; v[2*q+1] = a2.y;
                }
                ull pr[9];
                #pragma unroll
                for (int i = 0; i < 9; i++) pr[i] = pk2(v[i], v[i+1]);
                #pragma unroll
                for (int oc = 0; oc < 4; oc++){
                    const float* wp = &wsm[s][(ocg*4 + oc)*9 + r*3];
                    #pragma unroll
                    for (int kx = 0; kx < 3; kx++){
                        float wv = wp[kx];
                        ull wpair = pk2(wv, wv);
                        #pragma unroll
                        for (int j = 0; j < 4; j++)
                            acc[oc*4 + j] = fma2(wpair, pr[2*j + kx], acc[oc*4 + j]);
                    }
                }
            }
        }
    }
    #pragma unroll
    for (int oc = 0; oc < 4; oc++){
        int c = oc0 + ocg*4 + oc;
        float bv = bfus[c];
        #pragma unroll
        for (int j = 0; j < 4; j++){
            int x = xb + 2*j;
            float cs = g_csoft[(y >> 2)*HS + (x >> 2)];
            float2 av = upk(acc[oc*4 + j]);
            size_t pidx = (size_t)c*HH*WW + (size_t)y*WW + x;
            float2 an = *(const float2*)(anchor + pidx);
            float2 o;
            o.x = (av.x + bv)*cs + an.x;
            o.y = (av.y + bv)*cs + an.y;
            *(float2*)(out + pidx) = o;
        }
    }
}

// ---------------- launch ----------------
extern "C" void kernel_launch(void* const* d_in, const int* in_sizes, int n_in,
                              void* d_out, int out_size){
    (void)in_sizes; (void)n_in; (void)out_size;
    const float* curr   = (const float*)d_in[0];
    const float* idx1   = (const float*)d_in[1];
    const float* anchor = (const float*)d_in[2];
    const float* s1     = (const float*)d_in[3];
    const float* s2     = (const float*)d_in[4];
    const float* s3     = (const float*)d_in[5];
    const float* loc    = (const float*)d_in[6];
    const float* wtdw   = (const float*)d_in[7];
    const float* btdw   = (const float*)d_in[8];
    const float* lng    = (const float*)d_in[9];
    const float* lnb    = (const float*)d_in[10];
    const float* wtpw   = (const float*)d_in[11];
    const float* wfus   = (const float*)d_in[12];
    const float* bfus   = (const float*)d_in[13];
    float* out = (float*)d_out;

    cudaFuncSetAttribute(k_conv, cudaFuncAttributeMaxDynamicSharedMemorySize, 8*2704*4);

    k_grid<<<(TT*FN + 255)/256, 256>>>(loc);

    dim3 tb(32, 8);
    dim3 tg(FN/32, FL/32, 32);
    k_transpose<<<tg, tb>>>(idx1, s1, s2, s3);

    k_normfin<<<(TT*FN + 255)/256, 256>>>();
    k_cn     <<<FN, 256>>>(curr);
    k_conv   <<<dim3(64, NB), 192, 8*2704*4>>>(wtdw, btdw);
    k_ln     <<<dim3(FN/32, NB), 256>>>(lng, lnb, wtpw);
    k_mat    <<<FN, 256>>>();
    k_sg     <<<1152, 256>>>();
    k_fus    <<<dim3(3, 12, 8), 256>>>(wfus, bfus, anchor, out);
}

// round 4
// speedup vs baseline: 2.4680x; 1.8622x over previous
#include <cuda_runtime.h>
#include <cuda_fp16.h>
#include <math.h>

#define TT 8
#define HS 48
#define FN 2304          // 48*48
#define FL 1024          // C*S*S
#define HH 192
#define WW 192
#define NB 32            // n*t*G

// ---------------- scratch ----------------
__device__ float  g_iT [(size_t)TT*FN*FL];     // idx1 transposed (fp32: feeds argmax path)
__device__ __half g_s1T[(size_t)TT*FN*FL];     // value path: fp16 OK
__device__ __half g_s2T[(size_t)TT*FN*FL];
__device__ __half g_s3T[(size_t)TT*FN*FL];
__device__ float  g_CN [(size_t)FN*FL];
__device__ float  g_conv[(size_t)NB*256*FN];
__device__ float  g_gp [(size_t)NB*FN*2];
__device__ float  g_csoft[FN];
__device__ int    g_cidx [FN];
__device__ int    g_gidx [TT*FN];
__device__ float  g_inorm[TT*FN];
__device__ float  g_sspart[(size_t)32*TT*FN];
__device__ __half g_fusedT[(size_t)HH*WW*192]; // pixel-major fused features
__device__ uint4  g_wpk[4*9*12*32];            // fusion weights prepacked as mma A-fragments

// ---------------- K: nearest grid indices ----------------
__global__ void k_grid(const float* __restrict__ loc){
    int i = blockIdx.x*blockDim.x + threadIdx.x;
    if (i >= TT*FN) return;
    int t = i / FN, f = i - t*FN;
    float lx = loc[(t*2+0)*FN + f];
    float ly = loc[(t*2+1)*FN + f];
    int ix = __float2int_rn(lx);
    int iy = __float2int_rn(ly);
    bool valid = (ix>=0 && ix<HS && iy>=0 && iy<HS);
    g_gidx[i] = valid ? (iy*HS + ix) : -1;
}

// ---------------- K: prepack fusion weights into m16n8k16 A-fragments ----------------
__device__ __forceinline__ unsigned pkh(float a, float b){
    return (unsigned)__half_as_ushort(__float2half(a))
         | ((unsigned)__half_as_ushort(__float2half(b)) << 16);
}
__global__ void k_wpack(const float* __restrict__ wfus){
    int idx = blockIdx.x*blockDim.x + threadIdx.x;
    if (idx >= 4*9*12*32) return;
    int lane = idx & 31;
    int rest = idx >> 5;
    int kc = rest % 12; rest /= 12;
    int tap = rest % 9;
    int ocq = rest / 9;
    int g = lane >> 2, tg = lane & 3;
    int r0 = ocq*16 + g, r1 = r0 + 8;
    int k0 = kc*16 + tg*2;
    // W(oc, ic, tap) = wfus[(oc*192 + ic)*9 + tap]
    #define WF(r,k) wfus[((size_t)(r)*192 + (k))*9 + tap]
    uint4 u;
    u.x = pkh(WF(r0, k0),   WF(r0, k0+1));
    u.y = pkh(WF(r1, k0),   WF(r1, k0+1));
    u.z = pkh(WF(r0, k0+8), WF(r0, k0+9));
    u.w = pkh(WF(r1, k0+8), WF(r1, k0+9));
    #undef WF
    g_wpk[idx] = u;
}

// ---------------- K: tiled transpose + fused ||idx1||^2 partials ----------------
__global__ void k_transpose(const float* __restrict__ a0, const float* __restrict__ a1,
                            const float* __restrict__ a2, const float* __restrict__ a3){
    __shared__ float tile[32][33];
    int z = blockIdx.z;
    int which = z >> 3, t = z & 7;
    const float* src;
    __half* dsth = 0; float* dstf = 0;
    switch (which){
        case 0: src = a0; dstf = g_iT;  break;
        case 1: src = a1; dsth = g_s1T; break;
        case 2: src = a2; dsth = g_s2T; break;
        default:src = a3; dsth = g_s3T; break;
    }
    src += (size_t)t*FL*FN;
    size_t dbase = (size_t)t*FN*FL;
    int f0 = blockIdx.x*32, c0 = blockIdx.y*32;
    int tx = threadIdx.x, ty = threadIdx.y;
    #pragma unroll
    for (int r = 0; r < 32; r += 8)
        tile[ty+r][tx] = src[(size_t)(c0+ty+r)*FN + (f0+tx)];
    __syncthreads();
    if (which == 0){
        #pragma unroll
        for (int r = 0; r < 32; r += 8){
            float x = tile[tx][ty+r];
            dstf[dbase + (size_t)(f0+ty+r)*FL + (c0+tx)] = x;
            float s = x*x;
            #pragma unroll
            for (int o = 16; o > 0; o >>= 1) s += __shfl_xor_sync(~0u, s, o);
            if (tx == 0)
                g_sspart[(size_t)blockIdx.y*(TT*FN) + t*FN + (f0+ty+r)] = s;
        }
    } else {
        #pragma unroll
        for (int r = 0; r < 32; r += 8)
            dsth[dbase + (size_t)(f0+ty+r)*FL + (c0+tx)] = __float2half(tile[tx][ty+r]);
    }
}

// ---------------- K: finalize inverse norms ----------------
__global__ void k_normfin(){
    int i = blockIdx.x*blockDim.x + threadIdx.x;
    if (i >= TT*FN) return;
    float s = 0.f;
    #pragma unroll
    for (int k = 0; k < 32; k++) s += g_sspart[(size_t)k*(TT*FN) + i];
    g_inorm[i] = 1.0f / fmaxf(sqrtf(s), 1e-12f);
}

// ---------------- K: normalized unfold(curr), pixel-major ----------------
__global__ void k_cn(const float* __restrict__ curr){
    int f = blockIdx.x, tid = threadIdx.x;
    int fy = f / HS, fx = f - fy*HS;
    float v[4]; float ss = 0.f;
    #pragma unroll
    for (int k = 0; k < 4; k++){
        int cf = k*256 + tid;
        int c = cf >> 4, rem = cf & 15, sy = rem >> 2, sx = rem & 3;
        float x = curr[((size_t)c*HH + (fy*4+sy))*WW + (fx*4+sx)];
        v[k] = x; ss += x*x;
    }
    for (int o = 16; o > 0; o >>= 1) ss += __shfl_xor_sync(~0u, ss, o);
    __shared__ float ws[8]; __shared__ float invs;
    if ((tid & 31) == 0) ws[tid>>5] = ss;
    __syncthreads();
    if (tid == 0){
        float s = 0.f;
        #pragma unroll
        for (int k = 0; k < 8; k++) s += ws[k];
        invs = 1.0f / fmaxf(sqrtf(s), 1e-12f);
    }
    __syncthreads();
    float iv = invs;
    #pragma unroll
    for (int k = 0; k < 4; k++) g_CN[(size_t)f*FL + k*256 + tid] = v[k]*iv;
}

// ---------------- K: grouped 5x5 conv ----------------
__global__ void __launch_bounds__(192) k_conv(const float* __restrict__ wtdw,
                                              const float* __restrict__ btdw){
    extern __shared__ float p[];              // 8 planes x 52*52
    __shared__ float w[200];
    __shared__ float bsm[4];
    int oq = blockIdx.x;
    int b  = blockIdx.y;
    int t = b >> 2, g = b & 3;
    int tid = threadIdx.x;
    int o0 = oq*4;
    bool isQ = (o0 < 128);
    int ch0 = g*256 + 2*o0 - (isQ ? 0 : 256);
    for (int i = tid; i < 200; i += 192) w[i] = wtdw[(size_t)o0*50 + i];
    if (tid < 4) bsm[tid] = btdw[o0 + tid];
    for (int i = tid; i < 2704*2; i += 192){
        int pix = i >> 1, half = i & 1;
        int yy = pix/52 - 2, xx = pix%52 - 2;
        float4 v = make_float4(0.f,0.f,0.f,0.f);
        if (yy >= 0 && yy < HS && xx >= 0 && xx < HS){
            int f = yy*HS + xx;
            if (isQ){
                v = *(const float4*)(g_CN + (size_t)f*FL + ch0 + half*4);
            } else {
                int idx = g_gidx[t*FN + f];
                if (idx >= 0){
                    float inr = g_inorm[t*FN + idx];
                    v = *(const float4*)(g_iT + ((size_t)t*FN + idx)*FL + ch0 + half*4);
                    v.x *= inr; v.y *= inr; v.z *= inr; v.w *= inr;
                }
            }
        }
        int cb = half*4;
        p[(cb+0)*2704 + pix] = v.x;
        p[(cb+1)*2704 + pix] = v.y;
        p[(cb+2)*2704 + pix] = v.z;
        p[(cb+3)*2704 + pix] = v.w;
    }
    __syncthreads();
    int x  = tid % 48;
    int ys = tid / 48;
    float acc[4][12];
    #pragma unroll
    for (int o = 0; o < 4; o++)
        #pragma unroll
        for (int j = 0; j < 12; j++) acc[o][j] = 0.f;
    #pragma unroll
    for (int c = 0; c < 8; c++){
        const float* wb = w + (c>>1)*50 + (c&1)*25;
        const float* pc = p + c*2704;
        #pragma unroll
        for (int kx = 0; kx < 5; kx++){
            float v[16];
            #pragma unroll
            for (int r = 0; r < 16; r++) v[r] = pc[(ys*12 + r)*52 + x + kx];
            #pragma unroll
            for (int ky = 0; ky < 5; ky++){
                float wv = wb[ky*5 + kx];
                #pragma unroll
                for (int j = 0; j < 12; j++) acc[c>>1][j] += wv * v[j+ky];
            }
        }
    }
    #pragma unroll
    for (int o = 0; o < 4; o++){
        float bias = bsm[o];
        #pragma unroll
        for (int j = 0; j < 12; j++)
            g_conv[((size_t)b*256 + o0 + o)*FN + (ys*12 + j)*48 + x] = acc[o][j] + bias;
    }
}

// ---------------- K: LayerNorm + GELU + 1x1 conv + tanh -> coords ----------------
__global__ void k_ln(const float* __restrict__ lng, const float* __restrict__ lnb,
                     const float* __restrict__ wtpw){
    __shared__ float tile[256*33];
    __shared__ float sgam[256], sbet[256], w0[256], w1[256];
    int b = blockIdx.y;
    int pixbase = blockIdx.x * 32;
    int tid = threadIdx.x;
    sgam[tid] = lng[tid]; sbet[tid] = lnb[tid];
    w0[tid] = wtpw[tid];  w1[tid]  = wtpw[256 + tid];
    for (int i = tid; i < 256*32; i += 256){
        int ch = i >> 5, pp = i & 31;
        tile[ch*33 + pp] = g_conv[((size_t)b*256 + ch)*FN + pixbase + pp];
    }
    __syncthreads();
    int lane = tid & 31, wid = tid >> 5;
    for (int q = 0; q < 4; q++){
        int pp = wid*4 + q;
        float xv[8]; float s = 0.f, ss = 0.f;
        #pragma unroll
        for (int k = 0; k < 8; k++){
            float x = tile[(lane + 32*k)*33 + pp];
            xv[k] = x; s += x; ss += x*x;
        }
        for (int o = 16; o > 0; o >>= 1){
            s  += __shfl_xor_sync(~0u, s,  o);
            ss += __shfl_xor_sync(~0u, ss, o);
        }
        float mean = s * (1.0f/256.0f);
        float var  = ss * (1.0f/256.0f) - mean*mean;
        float rstd = rsqrtf(var + 1e-5f);
        float a0 = 0.f, a1 = 0.f;
        #pragma unroll
        for (int k = 0; k < 8; k++){
            int ch = lane + 32*k;
            float y = (xv[k] - mean)*rstd*sgam[ch] + sbet[ch];
            float gl = 0.5f*y*(1.0f + erff(y*0.70710678118654752f));
            a0 += gl*w0[ch]; a1 += gl*w1[ch];
        }
        for (int o = 16; o > 0; o >>= 1){
            a0 += __shfl_xor_sync(~0u, a0, o);
            a1 += __shfl_xor_sync(~0u, a1, o);
        }
        if (lane == 0){
            int pix = pixbase + pp;
            int py = pix / HS, px = pix - py*HS;
            float o0 = tanhf(a0) * (2.0f/48.0f);
            float o1 = tanhf(a1) * (2.0f/48.0f);
            float ry = (0.5f + py)*(2.0f/48.0f) - 1.0f;
            float rx = (0.5f + px)*(2.0f/48.0f) - 1.0f;
            g_gp[((size_t)b*FN + pix)*2 + 0] = (o1 + rx + 1.0f)*0.5f*47.0f;
            g_gp[((size_t)b*FN + pix)*2 + 1] = (o0 + ry + 1.0f)*0.5f*47.0f;
        }
    }
}

// ---------------- K: mat + max/argmax, warp-per-t (fp32 exact) ----------------
__global__ void k_mat(){
    int f = blockIdx.x, tid = threadIdx.x;
    __shared__ float cns[1024];
    __shared__ float part[8];
    #pragma unroll
    for (int k = 0; k < 4; k++) cns[k*256 + tid] = g_CN[(size_t)f*FL + k*256 + tid];
    __syncthreads();
    int w = tid >> 5, lane = tid & 31;
    float acc = 0.f;
    #pragma unroll
    for (int g = 0; g < 4; g++){
        int b = w*4 + g;
        float sx = g_gp[((size_t)b*FN + f)*2 + 0];
        float sy = g_gp[((size_t)b*FN + f)*2 + 1];
        float x0f = floorf(sx), y0f = floorf(sy);
        float wx = sx - x0f, wy = sy - y0f;
        int x0 = (int)x0f, y0 = (int)y0f;
        float vs[8];
        #pragma unroll
        for (int k = 0; k < 8; k++) vs[k] = 0.f;
        #pragma unroll
        for (int dy = 0; dy < 2; dy++){
            #pragma unroll
            for (int dx = 0; dx < 2; dx++){
                int cy = y0 + dy, cx = x0 + dx;
                if (cy >= 0 && cy < HS && cx >= 0 && cx < HS){
                    int idx = g_gidx[w*FN + cy*HS + cx];
                    if (idx >= 0){
                        float sc = ((dy ? wy : 1.0f-wy) * (dx ? wx : 1.0f-wx))
                                   * g_inorm[w*FN + idx];
                        const float* ip = g_iT + ((size_t)w*FN + idx)*FL + g*256;
                        #pragma unroll
                        for (int k = 0; k < 8; k++) vs[k] += sc * ip[k*32 + lane];
                    }
                }
            }
        }
        #pragma unroll
        for (int k = 0; k < 8; k++) acc += vs[k] * cns[g*256 + k*32 + lane];
    }
    for (int o = 16; o > 0; o >>= 1) acc += __shfl_xor_sync(~0u, acc, o);
    if (lane == 0) part[w] = acc;
    __syncthreads();
    if (tid == 0){
        float best = part[0]; int besti = 0;
        #pragma unroll
        for (int t = 1; t < 8; t++){
            if (part[t] > best){ best = part[t]; besti = t; }
        }
        g_csoft[f] = best; g_cidx[f] = besti;
    }
}

// ---------------- K: argmax-time bilinear gather -> g_fusedT pixel-major fp16 ----------------
__global__ void k_sg(){
    int f = blockIdx.x, tid = threadIdx.x;
    __shared__ __half sv[192][18];
    int t = g_cidx[f];
    int fy = f / HS, fx = f - fy*HS;
    int pxl = tid & 15;
    int crow = tid >> 4;
    #pragma unroll
    for (int g = 0; g < 4; g++){
        int b = t*4 + g;
        float sx = g_gp[((size_t)b*FN + f)*2 + 0];
        float sy = g_gp[((size_t)b*FN + f)*2 + 1];
        float x0f = floorf(sx), y0f = floorf(sy);
        float wx = sx - x0f, wy = sy - y0f;
        int x0 = (int)x0f, y0 = (int)y0f;
        float v0 = 0.f, v1 = 0.f, v2 = 0.f;
        #pragma unroll
        for (int dy = 0; dy < 2; dy++){
            #pragma unroll
            for (int dx = 0; dx < 2; dx++){
                int cy = y0 + dy, cx = x0 + dx;
                if (cy >= 0 && cy < HS && cx >= 0 && cx < HS){
                    int idx = g_gidx[t*FN + cy*HS + cx];
                    if (idx >= 0){
                        float wgt = (dy ? wy : 1.0f-wy) * (dx ? wx : 1.0f-wx);
                        size_t off = ((size_t)t*FN + idx)*FL + g*256 + tid;
                        v0 += wgt * __half2float(g_s1T[off]);
                        v1 += wgt * __half2float(g_s2T[off]);
                        v2 += wgt * __half2float(g_s3T[off]);
                    }
                }
            }
        }
        int c = g*16 + crow;
        sv[c      ][pxl] = __float2half(v0);
        sv[64  + c][pxl] = __float2half(v1);
        sv[128 + c][pxl] = __float2half(v2);
    }
    __syncthreads();
    unsigned* outp = (unsigned*)g_fusedT;
    #pragma unroll
    for (int it = 0; it < 6; it++){
        int i = tid + it*256;
        int px2 = i / 96, k = i - px2*96;
        unsigned u = (unsigned)__half_as_ushort(sv[2*k][px2])
                   | ((unsigned)__half_as_ushort(sv[2*k+1][px2]) << 16);
        int gx = fx*4 + (px2 & 3), gy = fy*4 + (px2 >> 2);
        outp[((size_t)(gy*WW + gx))*96 + k] = u;
    }
}

// ---------------- K: 3x3 fusion conv via mma.sync m16n8k16 (f16 in, f32 acc) ----------------
__device__ __forceinline__ void mma16816(float& d0, float& d1, float& d2, float& d3,
                                         unsigned a0, unsigned a1, unsigned a2, unsigned a3,
                                         unsigned b0, unsigned b1){
    asm volatile(
        "mma.sync.aligned.m16n8k16.row.col.f32.f16.f16.f32 "
        "{%0,%1,%2,%3},{%4,%5,%6,%7},{%8,%9},{%0,%1,%2,%3};\n"
        : "+f"(d0), "+f"(d1), "+f"(d2), "+f"(d3)
        : "r"(a0), "r"(a1), "r"(a2), "r"(a3), "r"(b0), "r"(b1));
}

__global__ void __launch_bounds__(256, 1) k_fus(const float* __restrict__ bfus,
                                                const float* __restrict__ anchor,
                                                float* __restrict__ out){
    extern __shared__ __half xs[];            // [6 rows][66 px][pitch 200 ch halves]
    const unsigned* xsw = (const unsigned*)xs;
    uint4* xs4 = (uint4*)xs;
    int tid = threadIdx.x;
    int X0 = blockIdx.x*64, Y0 = blockIdx.y*4;

    // stage input tile (rows Y0-1..Y0+4, px X0-1..X0+64), zero-padded OOB
    for (int i = tid; i < 6*66*24; i += 256){
        int k = i % 24; int pj = i / 24; int j = pj % 66; int r = pj / 66;
        int y = Y0 - 1 + r, x = X0 - 1 + j;
        uint4 v = make_uint4(0u,0u,0u,0u);
        if (y >= 0 && y < HH && x >= 0 && x < WW)
            v = *(const uint4*)(g_fusedT + ((size_t)(y*WW + x))*192 + k*8);
        xs4[(r*66 + j)*25 + k] = v;
    }
    __syncthreads();

    int wid = tid >> 5, lane = tid & 31;
    int g = lane >> 2, tg = lane & 3;
    int ocq = wid & 3, yh = wid >> 2;
    int laneoff = g*100 + tg;

    float acc[2][8][4];
    #pragma unroll
    for (int a = 0; a < 2; a++)
        #pragma unroll
        for (int bq = 0; bq < 8; bq++)
            #pragma unroll
            for (int c = 0; c < 4; c++) acc[a][bq][c] = 0.f;

    for (int tap = 0; tap < 9; tap++){
        int ky = tap / 3, kx = tap - ky*3;
        for (int kc = 0; kc < 12; kc++){
            uint4 aa = __ldg(&g_wpk[((ocq*9 + tap)*12 + kc)*32 + lane]);
            #pragma unroll
            for (int yl = 0; yl < 2; yl++){
                int rb = ((yh*2 + yl + ky)*66 + kx)*100 + kc*8 + laneoff;
                #pragma unroll
                for (int xt = 0; xt < 8; xt++){
                    unsigned b0 = xsw[rb + xt*800];
                    unsigned b1 = xsw[rb + xt*800 + 4];
                    mma16816(acc[yl][xt][0], acc[yl][xt][1], acc[yl][xt][2], acc[yl][xt][3],
                             aa.x, aa.y, aa.z, aa.w, b0, b1);
                }
            }
        }
    }

    int oc0 = ocq*16 + g;
    float bias0 = __ldg(&bfus[oc0]);
    float bias1 = __ldg(&bfus[oc0 + 8]);
    #pragma unroll
    for (int yl = 0; yl < 2; yl++){
        int y = Y0 + yh*2 + yl;
        #pragma unroll
        for (int xt = 0; xt < 8; xt++){
            int x = X0 + xt*8 + tg*2;
            float cs = g_csoft[(y >> 2)*HS + (x >> 2)];
            size_t p0 = ((size_t)oc0*HH + y)*WW + x;
            size_t p1 = ((size_t)(oc0+8)*HH + y)*WW + x;
            float2 an0 = *(const float2*)(anchor + p0);
            float2 an1 = *(const float2*)(anchor + p1);
            float2 o0, o1;
            o0.x = (acc[yl][xt][0] + bias0)*cs + an0.x;
            o0.y = (acc[yl][xt][1] + bias0)*cs + an0.y;
            o1.x = (acc[yl][xt][2] + bias1)*cs + an1.x;
            o1.y = (acc[yl][xt][3] + bias1)*cs + an1.y;
            *(float2*)(out + p0) = o0;
            *(float2*)(out + p1) = o1;
        }
    }
}

// ---------------- launch ----------------
extern "C" void kernel_launch(void* const* d_in, const int* in_sizes, int n_in,
                              void* d_out, int out_size){
    (void)in_sizes; (void)n_in; (void)out_size;
    const float* curr   = (const float*)d_in[0];
    const float* idx1   = (const float*)d_in[1];
    const float* anchor = (const float*)d_in[2];
    const float* s1     = (const float*)d_in[3];
    const float* s2     = (const float*)d_in[4];
    const float* s3     = (const float*)d_in[5];
    const float* loc    = (const float*)d_in[6];
    const float* wtdw   = (const float*)d_in[7];
    const float* btdw   = (const float*)d_in[8];
    const float* lng    = (const float*)d_in[9];
    const float* lnb    = (const float*)d_in[10];
    const float* wtpw   = (const float*)d_in[11];
    const float* wfus   = (const float*)d_in[12];
    const float* bfus   = (const float*)d_in[13];
    float* out = (float*)d_out;

    cudaFuncSetAttribute(k_conv, cudaFuncAttributeMaxDynamicSharedMemorySize, 8*2704*4);
    cudaFuncSetAttribute(k_fus,  cudaFuncAttributeMaxDynamicSharedMemorySize, 6*66*200*2);

    // order chosen so launch #4 (the one ncu captures) is k_transpose
    k_grid <<<(TT*FN + 255)/256, 256>>>(loc);
    k_cn   <<<FN, 256>>>(curr);
    k_wpack<<<54, 256>>>(wfus);

    dim3 tb(32, 8);
    dim3 tg(FN/32, FL/32, 32);
    k_transpose<<<tg, tb>>>(idx1, s1, s2, s3);

    k_normfin<<<(TT*FN + 255)/256, 256>>>();
    k_conv   <<<dim3(64, NB), 192, 8*2704*4>>>(wtdw, btdw);
    k_ln     <<<dim3(FN/32, NB), 256>>>(lng, lnb, wtpw);
    k_mat    <<<FN, 256>>>();
    k_sg     <<<FN, 256>>>();
    k_fus    <<<dim3(3, 48), 256, 6*66*200*2>>>(bfus, anchor, out);
}